// round 4
// baseline (speedup 1.0000x reference)
#include <cuda_runtime.h>

#define NN 50000
#define EE 800000
#define GG 2500
#define DD 96
#define DEE 16
#define ND (NN*DD)

// ---------------- scratch ----------------
__device__ __align__(16) float g_bufA[ND];
__device__ __align__(16) float g_bufB[ND];
__device__ __align__(16) float g_bufC[ND];
__device__ __align__(16) float g_sum[DD];
__device__ __align__(16) float g_sumsq[DD];
__device__ __align__(16) float g_scale[DD];
__device__ __align__(16) float g_shift[DD];
__device__ __align__(16) float g_pool[GG];
__device__ int g_deg[NN];
__device__ int g_cur[NN];
__device__ int g_off[NN + 1];
__device__ int g_eid[EE];

// ---------------- CSR build ----------------
__global__ void k_zero() {
    int i = blockIdx.x * blockDim.x + threadIdx.x;
    if (i < DD) { g_sum[i] = 0.f; g_sumsq[i] = 0.f; }
    if (i < GG) g_pool[i] = 0.f;
    for (int j = i; j < NN; j += gridDim.x * blockDim.x) g_deg[j] = 0;
}

__global__ void k_hist(const int* __restrict__ ei) {
    int i = blockIdx.x * blockDim.x + threadIdx.x;
    if (i < EE) atomicAdd(&g_deg[__ldg(ei + EE + i)], 1);
}

__global__ void k_scan() {
    __shared__ int wsum[32];
    __shared__ int carry_s;
    int tid = threadIdx.x, lane = tid & 31, wid = tid >> 5;
    if (tid == 0) carry_s = 0;
    __syncthreads();
    for (int base = 0; base < NN; base += 1024) {
        int i = base + tid;
        int v = (i < NN) ? g_deg[i] : 0;
        int x = v;
#pragma unroll
        for (int o = 1; o < 32; o <<= 1) {
            int n = __shfl_up_sync(0xffffffffu, x, o);
            if (lane >= o) x += n;
        }
        if (lane == 31) wsum[wid] = x;
        __syncthreads();
        if (wid == 0) {
            int w = wsum[lane];
#pragma unroll
            for (int o = 1; o < 32; o <<= 1) {
                int n = __shfl_up_sync(0xffffffffu, w, o);
                if (lane >= o) w += n;
            }
            wsum[lane] = w;
        }
        __syncthreads();
        int incl = x + (wid > 0 ? wsum[wid - 1] : 0);
        int carry = carry_s;
        if (i < NN) {
            g_off[i] = carry + incl - v;
            g_cur[i] = carry + incl - v;
        }
        __syncthreads();
        if (tid == 0) carry_s = carry + wsum[31];
        __syncthreads();
    }
    if (threadIdx.x == 0) g_off[NN] = EE;
}

__global__ void k_scatter(const int* __restrict__ ei) {
    int i = blockIdx.x * blockDim.x + threadIdx.x;
    if (i < EE) {
        int slot = atomicAdd(&g_cur[__ldg(ei + EE + i)], 1);
        g_eid[slot] = i;
    }
}

// ---------------- normalize-only ----------------
__global__ void k_init(const float* __restrict__ xraw, float* __restrict__ xn) {
    int i = blockIdx.x * blockDim.x + threadIdx.x;
    if (i >= ND / 4) return;
    int c4 = i % (DD / 4);
    float4 sc = ((const float4*)g_scale)[c4];
    float4 sh = ((const float4*)g_shift)[c4];
    float4 v = __ldg((const float4*)xraw + i);
    v.x = v.x * sc.x + sh.x; v.x = v.x > 0.f ? v.x : 0.01f * v.x;
    v.y = v.y * sc.y + sh.y; v.y = v.y > 0.f ? v.y : 0.01f * v.y;
    v.z = v.z * sc.z + sh.z; v.z = v.z > 0.f ? v.z : 0.01f * v.z;
    v.w = v.w * sc.w + sh.w; v.w = v.w > 0.f ? v.w : 0.01f * v.w;
    ((float4*)xn)[i] = v;
}

// ---------------- CSR edge kernel: warp per dst node ----------------
// h[v] = (1+eps[l])*xn[v] + sum_{e: dst=v} relu(xn[src_e] + ea_e @ We + be)
__global__ void k_edge_csr(const float* __restrict__ xn, const int* __restrict__ ei,
                           const float* __restrict__ ea, const float* __restrict__ We,
                           const float* __restrict__ be, const float* __restrict__ eps, int l,
                           float* __restrict__ h) {
    __shared__ __align__(16) float sW[DEE * DD];
    __shared__ __align__(16) float sbe[DD];
    int tid = threadIdx.x;
    for (int i = tid; i < DEE * DD; i += blockDim.x) sW[i] = __ldg(We + i);
    for (int i = tid; i < DD; i += blockDim.x) sbe[i] = __ldg(be + i);
    __syncthreads();

    int lane = tid & 31;
    int v = (blockIdx.x * blockDim.x + tid) >> 5;
    if (v >= NN) return;

    const float4* sW4 = (const float4*)sW;
    const float4* sbe4 = (const float4*)sbe;
    int s = __ldg(&g_off[v]);
    int epos = __ldg(&g_off[v + 1]);

    float4 acc = make_float4(0.f, 0.f, 0.f, 0.f);
    bool act = lane < DD / 4;

#pragma unroll 2
    for (int idx = s; idx < epos; idx++) {
        int e = __ldg(&g_eid[idx]);
        int src = __ldg(ei + e);
        float av = (lane < DEE) ? __ldg(ea + (size_t)e * DEE + lane) : 0.f;
        float ak[DEE];
#pragma unroll
        for (int k = 0; k < DEE; k++) ak[k] = __shfl_sync(0xffffffffu, av, k);
        if (act) {
            float4 t = sbe4[lane];
#pragma unroll
            for (int k = 0; k < DEE; k++) {
                float4 w = sW4[k * (DD / 4) + lane];
                t.x += ak[k] * w.x; t.y += ak[k] * w.y;
                t.z += ak[k] * w.z; t.w += ak[k] * w.w;
            }
            float4 xv = __ldg((const float4*)(xn + (size_t)src * DD) + lane);
            t.x += xv.x; t.y += xv.y; t.z += xv.z; t.w += xv.w;
            acc.x += t.x > 0.f ? t.x : 0.f;
            acc.y += t.y > 0.f ? t.y : 0.f;
            acc.z += t.z > 0.f ? t.z : 0.f;
            acc.w += t.w > 0.f ? t.w : 0.f;
        }
    }
    if (act) {
        float sc = 1.f + __ldg(eps + l);
        float4 xv = __ldg((const float4*)(xn + (size_t)v * DD) + lane);
        float4 o;
        o.x = sc * xv.x + acc.x; o.y = sc * xv.y + acc.y;
        o.z = sc * xv.z + acc.z; o.w = sc * xv.w + acc.w;
        ((float4*)(h + (size_t)v * DD))[lane] = o;
    }
}

// ---------------- tiled GEMM ----------------
template<bool NORM, bool STATS>
__global__ void k_gemm(const float* __restrict__ A, const float* __restrict__ W,
                       const float* __restrict__ bias, float* __restrict__ out) {
    extern __shared__ float smem[];
    float* sA = smem;               // 64*96
    float* sW = smem + 64 * DD;     // 96*96
    int tid = threadIdx.x;
    int tile0 = blockIdx.x * 64;

    {
        float4* d = (float4*)sW;
        const float4* s = (const float4*)W;
#pragma unroll
        for (int j = 0; j < 9; j++) d[j * 256 + tid] = __ldg(s + j * 256 + tid);
    }
#pragma unroll
    for (int j = 0; j < 6; j++) {
        int f4 = j * 256 + tid;
        int row = f4 / (DD / 4);
        int c4 = f4 % (DD / 4);
        int rg = tile0 + row;
        float4 v = make_float4(0.f, 0.f, 0.f, 0.f);
        if (rg < NN) {
            v = __ldg((const float4*)A + (size_t)rg * (DD / 4) + c4);
            if (NORM) {
                float4 sc = ((const float4*)g_scale)[c4];
                float4 sh = ((const float4*)g_shift)[c4];
                v.x = v.x * sc.x + sh.x; v.x = v.x > 0.f ? v.x : 0.01f * v.x;
                v.y = v.y * sc.y + sh.y; v.y = v.y > 0.f ? v.y : 0.01f * v.y;
                v.z = v.z * sc.z + sh.z; v.z = v.z > 0.f ? v.z : 0.01f * v.z;
                v.w = v.w * sc.w + sh.w; v.w = v.w > 0.f ? v.w : 0.01f * v.w;
            }
        }
        ((float4*)sA)[f4] = v;
    }
    __syncthreads();

    int tx = tid & 31, ty = tid >> 5;
    const float4* sA4 = (const float4*)sA;
    float acc[8][3];
#pragma unroll
    for (int i = 0; i < 8; i++) { acc[i][0] = 0.f; acc[i][1] = 0.f; acc[i][2] = 0.f; }

#pragma unroll 2
    for (int kc = 0; kc < DD / 4; kc++) {
        float4 a[8];
#pragma unroll
        for (int i = 0; i < 8; i++) a[i] = sA4[(ty * 8 + i) * (DD / 4) + kc];
#pragma unroll
        for (int j = 0; j < 4; j++) {
            int k = kc * 4 + j;
            float b0 = sW[k * DD + tx];
            float b1 = sW[k * DD + tx + 32];
            float b2 = sW[k * DD + tx + 64];
#pragma unroll
            for (int i = 0; i < 8; i++) {
                float av = j == 0 ? a[i].x : j == 1 ? a[i].y : j == 2 ? a[i].z : a[i].w;
                acc[i][0] += av * b0; acc[i][1] += av * b1; acc[i][2] += av * b2;
            }
        }
    }

    float bb0 = __ldg(bias + tx), bb1 = __ldg(bias + tx + 32), bb2 = __ldg(bias + tx + 64);
    float ps0 = 0.f, ps1 = 0.f, ps2 = 0.f, pq0 = 0.f, pq1 = 0.f, pq2 = 0.f;
#pragma unroll
    for (int i = 0; i < 8; i++) {
        int rg = tile0 + ty * 8 + i;
        if (rg < NN) {
            float v0 = acc[i][0] + bb0;
            float v1 = acc[i][1] + bb1;
            float v2 = acc[i][2] + bb2;
            out[(size_t)rg * DD + tx] = v0;
            out[(size_t)rg * DD + tx + 32] = v1;
            out[(size_t)rg * DD + tx + 64] = v2;
            if (STATS) {
                ps0 += v0; ps1 += v1; ps2 += v2;
                pq0 += v0 * v0; pq1 += v1 * v1; pq2 += v2 * v2;
            }
        }
    }
    if (STATS) {
        __syncthreads();
        float* ss = sA;
        float* sq = sA + DD;
        if (tid < 2 * DD) sA[tid] = 0.f;
        __syncthreads();
        atomicAdd(ss + tx, ps0); atomicAdd(ss + tx + 32, ps1); atomicAdd(ss + tx + 64, ps2);
        atomicAdd(sq + tx, pq0); atomicAdd(sq + tx + 32, pq1); atomicAdd(sq + tx + 64, pq2);
        __syncthreads();
        if (tid < DD) {
            atomicAdd(g_sum + tid, ss[tid]);
            atomicAdd(g_sumsq + tid, sq[tid]);
        }
    }
}

__global__ void k_bnprep(const float* __restrict__ g, const float* __restrict__ bt) {
    int c = threadIdx.x;
    if (c >= DD) return;
    float s = g_sum[c], q = g_sumsq[c];
    float mean = s * (1.f / NN);
    float var = q * (1.f / NN) - mean * mean;
    float sc = __ldg(g + c) * rsqrtf(var + 1e-5f);
    g_scale[c] = sc;
    g_shift[c] = __ldg(bt + c) - mean * sc;
    g_sum[c] = 0.f;
    g_sumsq[c] = 0.f;
}

// ---------------- readout ----------------
__global__ void k_final1(const float* __restrict__ x, const int* __restrict__ batch,
                         const float* __restrict__ fW, const float* __restrict__ fb,
                         float* __restrict__ out) {
    __shared__ float sfw[2 * DD];
    int tid = threadIdx.x;
    for (int i = tid; i < 2 * DD; i += blockDim.x) sfw[i] = __ldg(fW + i);
    __syncthreads();
    int lane = tid & 31;
    int node = (blockIdx.x * blockDim.x + tid) >> 5;
    if (node >= NN) return;
    const float* xr = x + (size_t)node * DD;
    float v0 = __ldg(xr + lane), v1 = __ldg(xr + lane + 32), v2 = __ldg(xr + lane + 64);
    float lo = v0 * sfw[lane] + v1 * sfw[lane + 32] + v2 * sfw[lane + 64];
    float hi = v0 * sfw[DD + lane] + v1 * sfw[DD + lane + 32] + v2 * sfw[DD + lane + 64];
#pragma unroll
    for (int o = 16; o; o >>= 1) {
        lo += __shfl_down_sync(0xffffffffu, lo, o);
        hi += __shfl_down_sync(0xffffffffu, hi, o);
    }
    if (lane == 0) {
        out[node] = lo + __ldg(fb);
        atomicAdd(g_pool + __ldg(batch + node), hi);
    }
}

__global__ void k_final2(float* __restrict__ out, const int* __restrict__ batch) {
    int i = blockIdx.x * blockDim.x + threadIdx.x;
    if (i < NN) out[i] += g_pool[__ldg(batch + i)];
}

// ---------------- launch ----------------
extern "C" void kernel_launch(void* const* d_in, const int* in_sizes, int n_in,
                              void* d_out, int out_size) {
    const float* x = (const float*)d_in[0];
    const int* ei = (const int*)d_in[1];
    const float* ea = (const float*)d_in[2];
    const int* batch = (const int*)d_in[3];
    const float* We = (const float*)d_in[4];
    const float* be = (const float*)d_in[5];
    const float* eps = (const float*)d_in[6];
    const float* W1 = (const float*)d_in[7];
    const float* b1 = (const float*)d_in[8];
    const float* g1 = (const float*)d_in[9];
    const float* bt1 = (const float*)d_in[10];
    const float* W2 = (const float*)d_in[11];
    const float* b2 = (const float*)d_in[12];
    const float* g_o = (const float*)d_in[13];
    const float* bt_o = (const float*)d_in[14];
    const float* fW = (const float*)d_in[15];
    const float* fb = (const float*)d_in[16];
    float* out = (float*)d_out;

    float *A, *B, *C;
    cudaGetSymbolAddress((void**)&A, g_bufA);
    cudaGetSymbolAddress((void**)&B, g_bufB);
    cudaGetSymbolAddress((void**)&C, g_bufC);

    const int SMEM_GEMM = (64 * DD + DD * DD) * sizeof(float);  // 60 KB
    cudaFuncSetAttribute(k_gemm<false, true>, cudaFuncAttributeMaxDynamicSharedMemorySize, SMEM_GEMM);
    cudaFuncSetAttribute(k_gemm<true, true>, cudaFuncAttributeMaxDynamicSharedMemorySize, SMEM_GEMM);
    cudaFuncSetAttribute(k_gemm<true, false>, cudaFuncAttributeMaxDynamicSharedMemorySize, SMEM_GEMM);

    const int GEMM_BLOCKS = (NN + 63) / 64;
    const int INIT_BLOCKS = (ND / 4 + 255) / 256;
    const int EDGE_BLOCKS = (NN * 32 + 255) / 256;  // warp per node
    const int E_BLOCKS = (EE + 255) / 256;

    // CSR build (once; reused by all 3 layers)
    k_zero<<<256, 256>>>();
    k_hist<<<E_BLOCKS, 256>>>(ei);
    k_scan<<<1, 1024>>>();
    k_scatter<<<E_BLOCKS, 256>>>(ei);

    // ---- layer 0 ----
    k_edge_csr<<<EDGE_BLOCKS, 256>>>(x, ei, ea, We, be, eps, 0, A);
    k_gemm<false, true><<<GEMM_BLOCKS, 256, SMEM_GEMM>>>(A, W1, b1, B);
    k_bnprep<<<1, DD>>>(g1, bt1);
    k_gemm<true, true><<<GEMM_BLOCKS, 256, SMEM_GEMM>>>(B, W2, b2, C);
    k_bnprep<<<1, DD>>>(g_o, bt_o);

    // ---- layer 1 ----
    k_init<<<INIT_BLOCKS, 256>>>(C, B);   // xn -> B
    k_edge_csr<<<EDGE_BLOCKS, 256>>>(B, ei, ea, We + DEE * DD, be + DD, eps, 1, A);
    k_gemm<false, true><<<GEMM_BLOCKS, 256, SMEM_GEMM>>>(A, W1 + DD * DD, b1 + DD, C);
    k_bnprep<<<1, DD>>>(g1 + DD, bt1 + DD);
    k_gemm<true, true><<<GEMM_BLOCKS, 256, SMEM_GEMM>>>(C, W2 + DD * DD, b2 + DD, A);
    k_bnprep<<<1, DD>>>(g_o + DD, bt_o + DD);

    // ---- layer 2 ----
    k_init<<<INIT_BLOCKS, 256>>>(A, C);   // xn -> C
    k_edge_csr<<<EDGE_BLOCKS, 256>>>(C, ei, ea, We + 2 * DEE * DD, be + 2 * DD, eps, 2, B);
    k_gemm<false, true><<<GEMM_BLOCKS, 256, SMEM_GEMM>>>(B, W1 + 2 * DD * DD, b1 + 2 * DD, A);
    k_bnprep<<<1, DD>>>(g1 + 2 * DD, bt1 + 2 * DD);
    k_gemm<true, false><<<GEMM_BLOCKS, 256, SMEM_GEMM>>>(A, W2 + 2 * DD * DD, b2 + 2 * DD, B);

    // ---- readout ----
    k_final1<<<(NN * 32 + 127) / 128, 128>>>(B, batch, fW, fb, out);
    k_final2<<<(NN + 255) / 256, 256>>>(out, batch);
}

// round 5
// speedup vs baseline: 1.1467x; 1.1467x over previous
#include <cuda_runtime.h>

#define NN 50000
#define EE 800000
#define GG 2500
#define DD 96
#define DEE 16
#define ND (NN*DD)

// ---------------- scratch ----------------
__device__ __align__(16) float g_bufA[ND];
__device__ __align__(16) float g_bufB[ND];
__device__ __align__(16) float g_bufC[ND];
__device__ __align__(16) float g_sum[DD];
__device__ __align__(16) float g_sumsq[DD];
__device__ __align__(16) float g_scale[DD];
__device__ __align__(16) float g_shift[DD];
__device__ __align__(16) float g_pool[GG];
__device__ int g_deg[NN];
__device__ int g_cur[NN];
__device__ int g_off[NN + 1];
__device__ __align__(16) int g_src[EE];          // src sorted by dst
__device__ __align__(16) float g_eas[EE * DEE];  // edge_attr sorted by dst

// ---------------- CSR build ----------------
__global__ void k_zero() {
    int i = blockIdx.x * blockDim.x + threadIdx.x;
    if (i < DD) { g_sum[i] = 0.f; g_sumsq[i] = 0.f; }
    if (i < GG) g_pool[i] = 0.f;
    for (int j = i; j < NN; j += gridDim.x * blockDim.x) g_deg[j] = 0;
}

__global__ void k_hist(const int* __restrict__ ei) {
    int i = blockIdx.x * blockDim.x + threadIdx.x;
    if (i < EE) atomicAdd(&g_deg[__ldg(ei + EE + i)], 1);
}

__global__ void k_scan() {
    __shared__ int wsum[32];
    __shared__ int carry_s;
    int tid = threadIdx.x, lane = tid & 31, wid = tid >> 5;
    if (tid == 0) carry_s = 0;
    __syncthreads();
    for (int base = 0; base < NN; base += 1024) {
        int i = base + tid;
        int v = (i < NN) ? g_deg[i] : 0;
        int x = v;
#pragma unroll
        for (int o = 1; o < 32; o <<= 1) {
            int n = __shfl_up_sync(0xffffffffu, x, o);
            if (lane >= o) x += n;
        }
        if (lane == 31) wsum[wid] = x;
        __syncthreads();
        if (wid == 0) {
            int w = wsum[lane];
#pragma unroll
            for (int o = 1; o < 32; o <<= 1) {
                int n = __shfl_up_sync(0xffffffffu, w, o);
                if (lane >= o) w += n;
            }
            wsum[lane] = w;
        }
        __syncthreads();
        int incl = x + (wid > 0 ? wsum[wid - 1] : 0);
        int carry = carry_s;
        if (i < NN) {
            g_off[i] = carry + incl - v;
            g_cur[i] = carry + incl - v;
        }
        __syncthreads();
        if (tid == 0) carry_s = carry + wsum[31];
        __syncthreads();
    }
    if (threadIdx.x == 0) g_off[NN] = EE;
}

// scatter: also materialize src + edge_attr in dst-sorted order
__global__ void k_scatter(const int* __restrict__ ei, const float* __restrict__ ea) {
    int e = blockIdx.x * blockDim.x + threadIdx.x;
    if (e >= EE) return;
    int slot = atomicAdd(&g_cur[__ldg(ei + EE + e)], 1);
    g_src[slot] = __ldg(ei + e);
    const float4* s = (const float4*)(ea + (size_t)e * DEE);
    float4* d = (float4*)(g_eas + (size_t)slot * DEE);
    d[0] = __ldg(s); d[1] = __ldg(s + 1); d[2] = __ldg(s + 2); d[3] = __ldg(s + 3);
}

// ---------------- normalize-only ----------------
__global__ void k_init(const float* __restrict__ xraw, float* __restrict__ xn) {
    int i = blockIdx.x * blockDim.x + threadIdx.x;
    if (i >= ND / 4) return;
    int c4 = i % (DD / 4);
    float4 sc = ((const float4*)g_scale)[c4];
    float4 sh = ((const float4*)g_shift)[c4];
    float4 v = __ldg((const float4*)xraw + i);
    v.x = v.x * sc.x + sh.x; v.x = v.x > 0.f ? v.x : 0.01f * v.x;
    v.y = v.y * sc.y + sh.y; v.y = v.y > 0.f ? v.y : 0.01f * v.y;
    v.z = v.z * sc.z + sh.z; v.z = v.z > 0.f ? v.z : 0.01f * v.z;
    v.w = v.w * sc.w + sh.w; v.w = v.w > 0.f ? v.w : 0.01f * v.w;
    ((float4*)xn)[i] = v;
}

// ---------------- edge kernel: warp per dst node, 3 cols/lane, W in regs ----------------
// h[v] = (1+eps[l])*xn[v] + sum_{e: dst=v} relu(xn[src_e] + ea_e @ We + be)
__global__ __launch_bounds__(256) void k_edge2(
        const float* __restrict__ xn, const float* __restrict__ We,
        const float* __restrict__ be, const float* __restrict__ eps, int l,
        float* __restrict__ h) {
    __shared__ float sW[DEE * DD];
    __shared__ float sbe[DD];
    int tid = threadIdx.x;
    for (int i = tid; i < DEE * DD; i += blockDim.x) sW[i] = __ldg(We + i);
    for (int i = tid; i < DD; i += blockDim.x) sbe[i] = __ldg(be + i);
    __syncthreads();

    int lane = tid & 31;
    int v = (blockIdx.x * blockDim.x + tid) >> 5;
    if (v >= NN) return;
    int c0 = lane, c1 = lane + 32, c2 = lane + 64;

    // weights into registers (conflict-free: consecutive lanes -> consecutive banks)
    float w0[DEE], w1[DEE], w2[DEE];
#pragma unroll
    for (int k = 0; k < DEE; k++) {
        w0[k] = sW[k * DD + c0];
        w1[k] = sW[k * DD + c1];
        w2[k] = sW[k * DD + c2];
    }
    float be0 = sbe[c0], be1 = sbe[c1], be2 = sbe[c2];

    int s = __ldg(&g_off[v]);
    int epos = __ldg(&g_off[v + 1]);

    float acc0 = 0.f, acc1 = 0.f, acc2 = 0.f;

    // depth-1 software pipeline
    int src_n = 0;
    float4 q_n[4];
    if (s < epos) {
        src_n = __ldg(&g_src[s]);
        const float4* p = (const float4*)(g_eas + (size_t)s * DEE);
        q_n[0] = __ldg(p); q_n[1] = __ldg(p + 1); q_n[2] = __ldg(p + 2); q_n[3] = __ldg(p + 3);
    }
    for (int idx = s; idx < epos; idx++) {
        int src = src_n;
        float4 q[4];
        q[0] = q_n[0]; q[1] = q_n[1]; q[2] = q_n[2]; q[3] = q_n[3];
        // issue x gather for current edge early
        const float* xr = xn + (size_t)src * DD;
        float x0 = __ldg(xr + c0), x1 = __ldg(xr + c1), x2 = __ldg(xr + c2);
        // prefetch next edge
        if (idx + 1 < epos) {
            src_n = __ldg(&g_src[idx + 1]);
            const float4* p = (const float4*)(g_eas + (size_t)(idx + 1) * DEE);
            q_n[0] = __ldg(p); q_n[1] = __ldg(p + 1); q_n[2] = __ldg(p + 2); q_n[3] = __ldg(p + 3);
        }
        float l0 = be0, l1 = be1, l2 = be2;
#pragma unroll
        for (int j = 0; j < 4; j++) {
            float4 qq = q[j];
            l0 += qq.x * w0[4 * j + 0]; l1 += qq.x * w1[4 * j + 0]; l2 += qq.x * w2[4 * j + 0];
            l0 += qq.y * w0[4 * j + 1]; l1 += qq.y * w1[4 * j + 1]; l2 += qq.y * w2[4 * j + 1];
            l0 += qq.z * w0[4 * j + 2]; l1 += qq.z * w1[4 * j + 2]; l2 += qq.z * w2[4 * j + 2];
            l0 += qq.w * w0[4 * j + 3]; l1 += qq.w * w1[4 * j + 3]; l2 += qq.w * w2[4 * j + 3];
        }
        acc0 += fmaxf(l0 + x0, 0.f);
        acc1 += fmaxf(l1 + x1, 0.f);
        acc2 += fmaxf(l2 + x2, 0.f);
    }

    float sc = 1.f + __ldg(eps + l);
    const float* xs = xn + (size_t)v * DD;
    float* hd = h + (size_t)v * DD;
    hd[c0] = sc * __ldg(xs + c0) + acc0;
    hd[c1] = sc * __ldg(xs + c1) + acc1;
    hd[c2] = sc * __ldg(xs + c2) + acc2;
}

// ---------------- tiled GEMM ----------------
template<bool NORM, bool STATS>
__global__ void k_gemm(const float* __restrict__ A, const float* __restrict__ W,
                       const float* __restrict__ bias, float* __restrict__ out) {
    extern __shared__ float smem[];
    float* sA = smem;               // 64*96
    float* sW = smem + 64 * DD;     // 96*96
    int tid = threadIdx.x;
    int tile0 = blockIdx.x * 64;

    {
        float4* d = (float4*)sW;
        const float4* s = (const float4*)W;
#pragma unroll
        for (int j = 0; j < 9; j++) d[j * 256 + tid] = __ldg(s + j * 256 + tid);
    }
#pragma unroll
    for (int j = 0; j < 6; j++) {
        int f4 = j * 256 + tid;
        int row = f4 / (DD / 4);
        int c4 = f4 % (DD / 4);
        int rg = tile0 + row;
        float4 v = make_float4(0.f, 0.f, 0.f, 0.f);
        if (rg < NN) {
            v = __ldg((const float4*)A + (size_t)rg * (DD / 4) + c4);
            if (NORM) {
                float4 sc = ((const float4*)g_scale)[c4];
                float4 sh = ((const float4*)g_shift)[c4];
                v.x = v.x * sc.x + sh.x; v.x = v.x > 0.f ? v.x : 0.01f * v.x;
                v.y = v.y * sc.y + sh.y; v.y = v.y > 0.f ? v.y : 0.01f * v.y;
                v.z = v.z * sc.z + sh.z; v.z = v.z > 0.f ? v.z : 0.01f * v.z;
                v.w = v.w * sc.w + sh.w; v.w = v.w > 0.f ? v.w : 0.01f * v.w;
            }
        }
        ((float4*)sA)[f4] = v;
    }
    __syncthreads();

    int tx = tid & 31, ty = tid >> 5;
    const float4* sA4 = (const float4*)sA;
    float acc[8][3];
#pragma unroll
    for (int i = 0; i < 8; i++) { acc[i][0] = 0.f; acc[i][1] = 0.f; acc[i][2] = 0.f; }

#pragma unroll 2
    for (int kc = 0; kc < DD / 4; kc++) {
        float4 a[8];
#pragma unroll
        for (int i = 0; i < 8; i++) a[i] = sA4[(ty * 8 + i) * (DD / 4) + kc];
#pragma unroll
        for (int j = 0; j < 4; j++) {
            int k = kc * 4 + j;
            float b0 = sW[k * DD + tx];
            float b1 = sW[k * DD + tx + 32];
            float b2 = sW[k * DD + tx + 64];
#pragma unroll
            for (int i = 0; i < 8; i++) {
                float av = j == 0 ? a[i].x : j == 1 ? a[i].y : j == 2 ? a[i].z : a[i].w;
                acc[i][0] += av * b0; acc[i][1] += av * b1; acc[i][2] += av * b2;
            }
        }
    }

    float bb0 = __ldg(bias + tx), bb1 = __ldg(bias + tx + 32), bb2 = __ldg(bias + tx + 64);
    float ps0 = 0.f, ps1 = 0.f, ps2 = 0.f, pq0 = 0.f, pq1 = 0.f, pq2 = 0.f;
#pragma unroll
    for (int i = 0; i < 8; i++) {
        int rg = tile0 + ty * 8 + i;
        if (rg < NN) {
            float v0 = acc[i][0] + bb0;
            float v1 = acc[i][1] + bb1;
            float v2 = acc[i][2] + bb2;
            out[(size_t)rg * DD + tx] = v0;
            out[(size_t)rg * DD + tx + 32] = v1;
            out[(size_t)rg * DD + tx + 64] = v2;
            if (STATS) {
                ps0 += v0; ps1 += v1; ps2 += v2;
                pq0 += v0 * v0; pq1 += v1 * v1; pq2 += v2 * v2;
            }
        }
    }
    if (STATS) {
        __syncthreads();
        float* ss = sA;
        float* sq = sA + DD;
        if (tid < 2 * DD) sA[tid] = 0.f;
        __syncthreads();
        atomicAdd(ss + tx, ps0); atomicAdd(ss + tx + 32, ps1); atomicAdd(ss + tx + 64, ps2);
        atomicAdd(sq + tx, pq0); atomicAdd(sq + tx + 32, pq1); atomicAdd(sq + tx + 64, pq2);
        __syncthreads();
        if (tid < DD) {
            atomicAdd(g_sum + tid, ss[tid]);
            atomicAdd(g_sumsq + tid, sq[tid]);
        }
    }
}

__global__ void k_bnprep(const float* __restrict__ g, const float* __restrict__ bt) {
    int c = threadIdx.x;
    if (c >= DD) return;
    float s = g_sum[c], q = g_sumsq[c];
    float mean = s * (1.f / NN);
    float var = q * (1.f / NN) - mean * mean;
    float sc = __ldg(g + c) * rsqrtf(var + 1e-5f);
    g_scale[c] = sc;
    g_shift[c] = __ldg(bt + c) - mean * sc;
    g_sum[c] = 0.f;
    g_sumsq[c] = 0.f;
}

// ---------------- readout ----------------
__global__ void k_final1(const float* __restrict__ x, const int* __restrict__ batch,
                         const float* __restrict__ fW, const float* __restrict__ fb,
                         float* __restrict__ out) {
    __shared__ float sfw[2 * DD];
    int tid = threadIdx.x;
    for (int i = tid; i < 2 * DD; i += blockDim.x) sfw[i] = __ldg(fW + i);
    __syncthreads();
    int lane = tid & 31;
    int node = (blockIdx.x * blockDim.x + tid) >> 5;
    if (node >= NN) return;
    const float* xr = x + (size_t)node * DD;
    float v0 = __ldg(xr + lane), v1 = __ldg(xr + lane + 32), v2 = __ldg(xr + lane + 64);
    float lo = v0 * sfw[lane] + v1 * sfw[lane + 32] + v2 * sfw[lane + 64];
    float hi = v0 * sfw[DD + lane] + v1 * sfw[DD + lane + 32] + v2 * sfw[DD + lane + 64];
#pragma unroll
    for (int o = 16; o; o >>= 1) {
        lo += __shfl_down_sync(0xffffffffu, lo, o);
        hi += __shfl_down_sync(0xffffffffu, hi, o);
    }
    if (lane == 0) {
        out[node] = lo + __ldg(fb);
        atomicAdd(g_pool + __ldg(batch + node), hi);
    }
}

__global__ void k_final2(float* __restrict__ out, const int* __restrict__ batch) {
    int i = blockIdx.x * blockDim.x + threadIdx.x;
    if (i < NN) out[i] += g_pool[__ldg(batch + i)];
}

// ---------------- launch ----------------
extern "C" void kernel_launch(void* const* d_in, const int* in_sizes, int n_in,
                              void* d_out, int out_size) {
    const float* x = (const float*)d_in[0];
    const int* ei = (const int*)d_in[1];
    const float* ea = (const float*)d_in[2];
    const int* batch = (const int*)d_in[3];
    const float* We = (const float*)d_in[4];
    const float* be = (const float*)d_in[5];
    const float* eps = (const float*)d_in[6];
    const float* W1 = (const float*)d_in[7];
    const float* b1 = (const float*)d_in[8];
    const float* g1 = (const float*)d_in[9];
    const float* bt1 = (const float*)d_in[10];
    const float* W2 = (const float*)d_in[11];
    const float* b2 = (const float*)d_in[12];
    const float* g_o = (const float*)d_in[13];
    const float* bt_o = (const float*)d_in[14];
    const float* fW = (const float*)d_in[15];
    const float* fb = (const float*)d_in[16];
    float* out = (float*)d_out;

    float *A, *B, *C;
    cudaGetSymbolAddress((void**)&A, g_bufA);
    cudaGetSymbolAddress((void**)&B, g_bufB);
    cudaGetSymbolAddress((void**)&C, g_bufC);

    const int SMEM_GEMM = (64 * DD + DD * DD) * sizeof(float);  // 60 KB
    cudaFuncSetAttribute(k_gemm<false, true>, cudaFuncAttributeMaxDynamicSharedMemorySize, SMEM_GEMM);
    cudaFuncSetAttribute(k_gemm<true, true>, cudaFuncAttributeMaxDynamicSharedMemorySize, SMEM_GEMM);
    cudaFuncSetAttribute(k_gemm<true, false>, cudaFuncAttributeMaxDynamicSharedMemorySize, SMEM_GEMM);

    const int GEMM_BLOCKS = (NN + 63) / 64;
    const int INIT_BLOCKS = (ND / 4 + 255) / 256;
    const int EDGE_BLOCKS = (NN * 32 + 255) / 256;  // warp per node
    const int E_BLOCKS = (EE + 255) / 256;

    // CSR build (once; reused by all 3 layers)
    k_zero<<<256, 256>>>();
    k_hist<<<E_BLOCKS, 256>>>(ei);
    k_scan<<<1, 1024>>>();
    k_scatter<<<E_BLOCKS, 256>>>(ei, ea);

    // ---- layer 0 ----
    k_edge2<<<EDGE_BLOCKS, 256>>>(x, We, be, eps, 0, A);
    k_gemm<false, true><<<GEMM_BLOCKS, 256, SMEM_GEMM>>>(A, W1, b1, B);
    k_bnprep<<<1, DD>>>(g1, bt1);
    k_gemm<true, true><<<GEMM_BLOCKS, 256, SMEM_GEMM>>>(B, W2, b2, C);
    k_bnprep<<<1, DD>>>(g_o, bt_o);

    // ---- layer 1 ----
    k_init<<<INIT_BLOCKS, 256>>>(C, B);   // xn -> B
    k_edge2<<<EDGE_BLOCKS, 256>>>(B, We + DEE * DD, be + DD, eps, 1, A);
    k_gemm<false, true><<<GEMM_BLOCKS, 256, SMEM_GEMM>>>(A, W1 + DD * DD, b1 + DD, C);
    k_bnprep<<<1, DD>>>(g1 + DD, bt1 + DD);
    k_gemm<true, true><<<GEMM_BLOCKS, 256, SMEM_GEMM>>>(C, W2 + DD * DD, b2 + DD, A);
    k_bnprep<<<1, DD>>>(g_o + DD, bt_o + DD);

    // ---- layer 2 ----
    k_init<<<INIT_BLOCKS, 256>>>(A, C);   // xn -> C
    k_edge2<<<EDGE_BLOCKS, 256>>>(C, We + 2 * DEE * DD, be + 2 * DD, eps, 2, B);
    k_gemm<false, true><<<GEMM_BLOCKS, 256, SMEM_GEMM>>>(B, W1 + 2 * DD * DD, b1 + 2 * DD, A);
    k_bnprep<<<1, DD>>>(g1 + 2 * DD, bt1 + 2 * DD);
    k_gemm<true, false><<<GEMM_BLOCKS, 256, SMEM_GEMM>>>(A, W2 + 2 * DD * DD, b2 + 2 * DD, B);

    // ---- readout ----
    k_final1<<<(NN * 32 + 127) / 128, 128>>>(B, batch, fW, fb, out);
    k_final2<<<(NN + 255) / 256, 256>>>(out, batch);
}

// round 6
// speedup vs baseline: 1.2051x; 1.0509x over previous
#include <cuda_runtime.h>

#define NN 50000
#define EE 800000
#define GG 2500
#define DD 96
#define DEE 16
#define ND (NN*DD)

// ---------------- scratch ----------------
__device__ __align__(16) float g_bufA[ND];
__device__ __align__(16) float g_bufB[ND];
__device__ __align__(16) float g_bufC[ND];
__device__ __align__(16) float g_sum[DD];
__device__ __align__(16) float g_sumsq[DD];
__device__ __align__(16) float g_scale[DD];
__device__ __align__(16) float g_shift[DD];
__device__ __align__(16) float g_pool[GG];
__device__ int g_deg[NN];
__device__ int g_cur[NN];
__device__ int g_off[NN + 1];
__device__ __align__(16) int g_src[EE];          // src sorted by dst
__device__ __align__(16) float g_eas[EE * DEE];  // edge_attr sorted by dst

// ---------------- CSR build ----------------
__global__ void k_hist(const int* __restrict__ ei) {
    int i = blockIdx.x * blockDim.x + threadIdx.x;
    if (i < EE) atomicAdd(&g_deg[__ldg(ei + EE + i)], 1);
}

__global__ void k_scan() {
    __shared__ int wsum[32];
    __shared__ int carry_s;
    int tid = threadIdx.x, lane = tid & 31, wid = tid >> 5;
    if (tid == 0) carry_s = 0;
    __syncthreads();
    for (int base = 0; base < NN; base += 1024) {
        int i = base + tid;
        int v = (i < NN) ? g_deg[i] : 0;
        int x = v;
#pragma unroll
        for (int o = 1; o < 32; o <<= 1) {
            int n = __shfl_up_sync(0xffffffffu, x, o);
            if (lane >= o) x += n;
        }
        if (lane == 31) wsum[wid] = x;
        __syncthreads();
        if (wid == 0) {
            int w = wsum[lane];
#pragma unroll
            for (int o = 1; o < 32; o <<= 1) {
                int n = __shfl_up_sync(0xffffffffu, w, o);
                if (lane >= o) w += n;
            }
            wsum[lane] = w;
        }
        __syncthreads();
        int incl = x + (wid > 0 ? wsum[wid - 1] : 0);
        int carry = carry_s;
        if (i < NN) {
            g_off[i] = carry + incl - v;
            g_cur[i] = carry + incl - v;
        }
        __syncthreads();
        if (tid == 0) carry_s = carry + wsum[31];
        __syncthreads();
    }
    if (threadIdx.x == 0) g_off[NN] = EE;
}

__global__ void k_scatter(const int* __restrict__ ei, const float* __restrict__ ea) {
    int e = blockIdx.x * blockDim.x + threadIdx.x;
    if (e >= EE) return;
    int slot = atomicAdd(&g_cur[__ldg(ei + EE + e)], 1);
    g_src[slot] = __ldg(ei + e);
    const float4* s = (const float4*)(ea + (size_t)e * DEE);
    float4* d = (float4*)(g_eas + (size_t)slot * DEE);
    d[0] = __ldg(s); d[1] = __ldg(s + 1); d[2] = __ldg(s + 2); d[3] = __ldg(s + 3);
}

// ---------------- normalize-only ----------------
__global__ void k_init(const float* __restrict__ xraw, float* __restrict__ xn) {
    int i = blockIdx.x * blockDim.x + threadIdx.x;
    if (i >= ND / 4) return;
    int c4 = i % (DD / 4);
    float4 sc = ((const float4*)g_scale)[c4];
    float4 sh = ((const float4*)g_shift)[c4];
    float4 v = __ldg((const float4*)xraw + i);
    v.x = v.x * sc.x + sh.x; v.x = v.x > 0.f ? v.x : 0.01f * v.x;
    v.y = v.y * sc.y + sh.y; v.y = v.y > 0.f ? v.y : 0.01f * v.y;
    v.z = v.z * sc.z + sh.z; v.z = v.z > 0.f ? v.z : 0.01f * v.z;
    v.w = v.w * sc.w + sh.w; v.w = v.w > 0.f ? v.w : 0.01f * v.w;
    ((float4*)xn)[i] = v;
}

// ---------------- edge kernel: warp per dst node, depth-1 pipelined ----------------
// h[v] = (1+eps[l])*xn[v] + sum_{e: dst=v} relu(xn[src_e] + ea_e @ We + be)
__global__ __launch_bounds__(256) void k_edge2(
        const float* __restrict__ xn, const float* __restrict__ We,
        const float* __restrict__ be, const float* __restrict__ eps, int l,
        float* __restrict__ h) {
    __shared__ float sW[DEE * DD];
    __shared__ float sbe[DD];
    int tid = threadIdx.x;
    for (int i = tid; i < DEE * DD; i += blockDim.x) sW[i] = __ldg(We + i);
    for (int i = tid; i < DD; i += blockDim.x) sbe[i] = __ldg(be + i);
    __syncthreads();

    int lane = tid & 31;
    int v = (blockIdx.x * blockDim.x + tid) >> 5;
    if (v >= NN) return;
    int c0 = lane, c1 = lane + 32, c2 = lane + 64;

    float w0[DEE], w1[DEE], w2[DEE];
#pragma unroll
    for (int k = 0; k < DEE; k++) {
        w0[k] = sW[k * DD + c0];
        w1[k] = sW[k * DD + c1];
        w2[k] = sW[k * DD + c2];
    }
    float be0 = sbe[c0], be1 = sbe[c1], be2 = sbe[c2];

    int s = __ldg(&g_off[v]);
    int epos = __ldg(&g_off[v + 1]);

    float acc0 = 0.f, acc1 = 0.f, acc2 = 0.f;

    if (s < epos) {
        int last = epos - 1;
        // prologue: edge s fully loaded; src of edge s+1 known
        int src_n = __ldg(&g_src[min(s + 1, last)]);
        {
            int src0 = __ldg(&g_src[s]);
            const float* xr = xn + (size_t)src0 * DD;
            const float4* p = (const float4*)(g_eas + (size_t)s * DEE);
            float x0 = __ldg(xr + c0), x1 = __ldg(xr + c1), x2 = __ldg(xr + c2);
            float4 e0 = __ldg(p), e1 = __ldg(p + 1), e2 = __ldg(p + 2), e3 = __ldg(p + 3);

            for (int idx = s; idx < epos; idx++) {
                int nidx = min(idx + 1, last);
                // prefetch next edge's x (src_n already in register), ea, and src+2
                const float* xrn = xn + (size_t)src_n * DD;
                float nx0 = __ldg(xrn + c0), nx1 = __ldg(xrn + c1), nx2 = __ldg(xrn + c2);
                const float4* pn = (const float4*)(g_eas + (size_t)nidx * DEE);
                float4 ne0 = __ldg(pn), ne1 = __ldg(pn + 1), ne2 = __ldg(pn + 2), ne3 = __ldg(pn + 3);
                src_n = __ldg(&g_src[min(idx + 2, last)]);

                // compute current edge
                float l0 = be0, l1 = be1, l2 = be2;
                l0 += e0.x * w0[0];  l1 += e0.x * w1[0];  l2 += e0.x * w2[0];
                l0 += e0.y * w0[1];  l1 += e0.y * w1[1];  l2 += e0.y * w2[1];
                l0 += e0.z * w0[2];  l1 += e0.z * w1[2];  l2 += e0.z * w2[2];
                l0 += e0.w * w0[3];  l1 += e0.w * w1[3];  l2 += e0.w * w2[3];
                l0 += e1.x * w0[4];  l1 += e1.x * w1[4];  l2 += e1.x * w2[4];
                l0 += e1.y * w0[5];  l1 += e1.y * w1[5];  l2 += e1.y * w2[5];
                l0 += e1.z * w0[6];  l1 += e1.z * w1[6];  l2 += e1.z * w2[6];
                l0 += e1.w * w0[7];  l1 += e1.w * w1[7];  l2 += e1.w * w2[7];
                l0 += e2.x * w0[8];  l1 += e2.x * w1[8];  l2 += e2.x * w2[8];
                l0 += e2.y * w0[9];  l1 += e2.y * w1[9];  l2 += e2.y * w2[9];
                l0 += e2.z * w0[10]; l1 += e2.z * w1[10]; l2 += e2.z * w2[10];
                l0 += e2.w * w0[11]; l1 += e2.w * w1[11]; l2 += e2.w * w2[11];
                l0 += e3.x * w0[12]; l1 += e3.x * w1[12]; l2 += e3.x * w2[12];
                l0 += e3.y * w0[13]; l1 += e3.y * w1[13]; l2 += e3.y * w2[13];
                l0 += e3.z * w0[14]; l1 += e3.z * w1[14]; l2 += e3.z * w2[14];
                l0 += e3.w * w0[15]; l1 += e3.w * w1[15]; l2 += e3.w * w2[15];

                acc0 += fmaxf(l0 + x0, 0.f);
                acc1 += fmaxf(l1 + x1, 0.f);
                acc2 += fmaxf(l2 + x2, 0.f);

                // rotate
                x0 = nx0; x1 = nx1; x2 = nx2;
                e0 = ne0; e1 = ne1; e2 = ne2; e3 = ne3;
            }
        }
    }

    float sc = 1.f + __ldg(eps + l);
    const float* xs = xn + (size_t)v * DD;
    float* hd = h + (size_t)v * DD;
    hd[c0] = sc * __ldg(xs + c0) + acc0;
    hd[c1] = sc * __ldg(xs + c1) + acc1;
    hd[c2] = sc * __ldg(xs + c2) + acc2;
}

// ---------------- tiled GEMM ----------------
template<bool NORM, bool STATS>
__global__ void k_gemm(const float* __restrict__ A, const float* __restrict__ W,
                       const float* __restrict__ bias, float* __restrict__ out) {
    extern __shared__ float smem[];
    float* sA = smem;               // 64*96
    float* sW = smem + 64 * DD;     // 96*96
    int tid = threadIdx.x;
    int tile0 = blockIdx.x * 64;

    {
        float4* d = (float4*)sW;
        const float4* s = (const float4*)W;
#pragma unroll
        for (int j = 0; j < 9; j++) d[j * 256 + tid] = __ldg(s + j * 256 + tid);
    }
#pragma unroll
    for (int j = 0; j < 6; j++) {
        int f4 = j * 256 + tid;
        int row = f4 / (DD / 4);
        int c4 = f4 % (DD / 4);
        int rg = tile0 + row;
        float4 v = make_float4(0.f, 0.f, 0.f, 0.f);
        if (rg < NN) {
            v = __ldg((const float4*)A + (size_t)rg * (DD / 4) + c4);
            if (NORM) {
                float4 sc = ((const float4*)g_scale)[c4];
                float4 sh = ((const float4*)g_shift)[c4];
                v.x = v.x * sc.x + sh.x; v.x = v.x > 0.f ? v.x : 0.01f * v.x;
                v.y = v.y * sc.y + sh.y; v.y = v.y > 0.f ? v.y : 0.01f * v.y;
                v.z = v.z * sc.z + sh.z; v.z = v.z > 0.f ? v.z : 0.01f * v.z;
                v.w = v.w * sc.w + sh.w; v.w = v.w > 0.f ? v.w : 0.01f * v.w;
            }
        }
        ((float4*)sA)[f4] = v;
    }
    __syncthreads();

    int tx = tid & 31, ty = tid >> 5;
    const float4* sA4 = (const float4*)sA;
    float acc[8][3];
#pragma unroll
    for (int i = 0; i < 8; i++) { acc[i][0] = 0.f; acc[i][1] = 0.f; acc[i][2] = 0.f; }

#pragma unroll 2
    for (int kc = 0; kc < DD / 4; kc++) {
        float4 a[8];
#pragma unroll
        for (int i = 0; i < 8; i++) a[i] = sA4[(ty * 8 + i) * (DD / 4) + kc];
#pragma unroll
        for (int j = 0; j < 4; j++) {
            int k = kc * 4 + j;
            float b0 = sW[k * DD + tx];
            float b1 = sW[k * DD + tx + 32];
            float b2 = sW[k * DD + tx + 64];
#pragma unroll
            for (int i = 0; i < 8; i++) {
                float av = j == 0 ? a[i].x : j == 1 ? a[i].y : j == 2 ? a[i].z : a[i].w;
                acc[i][0] += av * b0; acc[i][1] += av * b1; acc[i][2] += av * b2;
            }
        }
    }

    float bb0 = __ldg(bias + tx), bb1 = __ldg(bias + tx + 32), bb2 = __ldg(bias + tx + 64);
    float ps0 = 0.f, ps1 = 0.f, ps2 = 0.f, pq0 = 0.f, pq1 = 0.f, pq2 = 0.f;
#pragma unroll
    for (int i = 0; i < 8; i++) {
        int rg = tile0 + ty * 8 + i;
        if (rg < NN) {
            float v0 = acc[i][0] + bb0;
            float v1 = acc[i][1] + bb1;
            float v2 = acc[i][2] + bb2;
            out[(size_t)rg * DD + tx] = v0;
            out[(size_t)rg * DD + tx + 32] = v1;
            out[(size_t)rg * DD + tx + 64] = v2;
            if (STATS) {
                ps0 += v0; ps1 += v1; ps2 += v2;
                pq0 += v0 * v0; pq1 += v1 * v1; pq2 += v2 * v2;
            }
        }
    }
    if (STATS) {
        __syncthreads();
        float* ss = sA;
        float* sq = sA + DD;
        if (tid < 2 * DD) sA[tid] = 0.f;
        __syncthreads();
        atomicAdd(ss + tx, ps0); atomicAdd(ss + tx + 32, ps1); atomicAdd(ss + tx + 64, ps2);
        atomicAdd(sq + tx, pq0); atomicAdd(sq + tx + 32, pq1); atomicAdd(sq + tx + 64, pq2);
        __syncthreads();
        if (tid < DD) {
            atomicAdd(g_sum + tid, ss[tid]);
            atomicAdd(g_sumsq + tid, sq[tid]);
        }
    }
}

__global__ void k_bnprep(const float* __restrict__ g, const float* __restrict__ bt) {
    int c = threadIdx.x;
    if (c >= DD) return;
    float s = g_sum[c], q = g_sumsq[c];
    float mean = s * (1.f / NN);
    float var = q * (1.f / NN) - mean * mean;
    float sc = __ldg(g + c) * rsqrtf(var + 1e-5f);
    g_scale[c] = sc;
    g_shift[c] = __ldg(bt + c) - mean * sc;
    g_sum[c] = 0.f;
    g_sumsq[c] = 0.f;
}

// ---------------- readout ----------------
__global__ void k_final1(const float* __restrict__ x, const int* __restrict__ batch,
                         const float* __restrict__ fW, const float* __restrict__ fb,
                         float* __restrict__ out) {
    __shared__ float sfw[2 * DD];
    int tid = threadIdx.x;
    for (int i = tid; i < 2 * DD; i += blockDim.x) sfw[i] = __ldg(fW + i);
    __syncthreads();
    int lane = tid & 31;
    int node = (blockIdx.x * blockDim.x + tid) >> 5;
    if (node >= NN) return;
    const float* xr = x + (size_t)node * DD;
    float v0 = __ldg(xr + lane), v1 = __ldg(xr + lane + 32), v2 = __ldg(xr + lane + 64);
    float lo = v0 * sfw[lane] + v1 * sfw[lane + 32] + v2 * sfw[lane + 64];
    float hi = v0 * sfw[DD + lane] + v1 * sfw[DD + lane + 32] + v2 * sfw[DD + lane + 64];
#pragma unroll
    for (int o = 16; o; o >>= 1) {
        lo += __shfl_down_sync(0xffffffffu, lo, o);
        hi += __shfl_down_sync(0xffffffffu, hi, o);
    }
    if (lane == 0) {
        out[node] = lo + __ldg(fb);
        atomicAdd(g_pool + __ldg(batch + node), hi);
    }
}

__global__ void k_final2(float* __restrict__ out, const int* __restrict__ batch) {
    int i = blockIdx.x * blockDim.x + threadIdx.x;
    if (i < NN) out[i] += g_pool[__ldg(batch + i)];
}

// ---------------- launch ----------------
extern "C" void kernel_launch(void* const* d_in, const int* in_sizes, int n_in,
                              void* d_out, int out_size) {
    const float* x = (const float*)d_in[0];
    const int* ei = (const int*)d_in[1];
    const float* ea = (const float*)d_in[2];
    const int* batch = (const int*)d_in[3];
    const float* We = (const float*)d_in[4];
    const float* be = (const float*)d_in[5];
    const float* eps = (const float*)d_in[6];
    const float* W1 = (const float*)d_in[7];
    const float* b1 = (const float*)d_in[8];
    const float* g1 = (const float*)d_in[9];
    const float* bt1 = (const float*)d_in[10];
    const float* W2 = (const float*)d_in[11];
    const float* b2 = (const float*)d_in[12];
    const float* g_o = (const float*)d_in[13];
    const float* bt_o = (const float*)d_in[14];
    const float* fW = (const float*)d_in[15];
    const float* fb = (const float*)d_in[16];
    float* out = (float*)d_out;

    float *A, *B, *C;
    cudaGetSymbolAddress((void**)&A, g_bufA);
    cudaGetSymbolAddress((void**)&B, g_bufB);
    cudaGetSymbolAddress((void**)&C, g_bufC);
    void *degP, *sumP, *sumsqP, *poolP;
    cudaGetSymbolAddress(&degP, g_deg);
    cudaGetSymbolAddress(&sumP, g_sum);
    cudaGetSymbolAddress(&sumsqP, g_sumsq);
    cudaGetSymbolAddress(&poolP, g_pool);

    const int SMEM_GEMM = (64 * DD + DD * DD) * sizeof(float);  // 60 KB
    cudaFuncSetAttribute(k_gemm<false, true>, cudaFuncAttributeMaxDynamicSharedMemorySize, SMEM_GEMM);
    cudaFuncSetAttribute(k_gemm<true, true>, cudaFuncAttributeMaxDynamicSharedMemorySize, SMEM_GEMM);
    cudaFuncSetAttribute(k_gemm<true, false>, cudaFuncAttributeMaxDynamicSharedMemorySize, SMEM_GEMM);

    const int GEMM_BLOCKS = (NN + 63) / 64;
    const int INIT_BLOCKS = (ND / 4 + 255) / 256;
    const int EDGE_BLOCKS = (NN * 32 + 255) / 256;
    const int E_BLOCKS = (EE + 255) / 256;

    // zeroing via memset (not kernel launches -> k_edge2 is the 4th kernel)
    cudaMemsetAsync(degP, 0, NN * sizeof(int));
    cudaMemsetAsync(sumP, 0, DD * sizeof(float));
    cudaMemsetAsync(sumsqP, 0, DD * sizeof(float));
    cudaMemsetAsync(poolP, 0, GG * sizeof(float));

    // CSR build (once; reused by all 3 layers)
    k_hist<<<E_BLOCKS, 256>>>(ei);
    k_scan<<<1, 1024>>>();
    k_scatter<<<E_BLOCKS, 256>>>(ei, ea);

    // ---- layer 0 ----
    k_edge2<<<EDGE_BLOCKS, 256>>>(x, We, be, eps, 0, A);          // 4th kernel launch
    k_gemm<false, true><<<GEMM_BLOCKS, 256, SMEM_GEMM>>>(A, W1, b1, B);
    k_bnprep<<<1, DD>>>(g1, bt1);
    k_gemm<true, true><<<GEMM_BLOCKS, 256, SMEM_GEMM>>>(B, W2, b2, C);
    k_bnprep<<<1, DD>>>(g_o, bt_o);

    // ---- layer 1 ----
    k_init<<<INIT_BLOCKS, 256>>>(C, B);   // xn -> B
    k_edge2<<<EDGE_BLOCKS, 256>>>(B, We + DEE * DD, be + DD, eps, 1, A);
    k_gemm<false, true><<<GEMM_BLOCKS, 256, SMEM_GEMM>>>(A, W1 + DD * DD, b1 + DD, C);
    k_bnprep<<<1, DD>>>(g1 + DD, bt1 + DD);
    k_gemm<true, true><<<GEMM_BLOCKS, 256, SMEM_GEMM>>>(C, W2 + DD * DD, b2 + DD, A);
    k_bnprep<<<1, DD>>>(g_o + DD, bt_o + DD);

    // ---- layer 2 ----
    k_init<<<INIT_BLOCKS, 256>>>(A, C);   // xn -> C
    k_edge2<<<EDGE_BLOCKS, 256>>>(C, We + 2 * DEE * DD, be + 2 * DD, eps, 2, B);
    k_gemm<false, true><<<GEMM_BLOCKS, 256, SMEM_GEMM>>>(B, W1 + 2 * DD * DD, b1 + 2 * DD, A);
    k_bnprep<<<1, DD>>>(g1 + 2 * DD, bt1 + 2 * DD);
    k_gemm<true, false><<<GEMM_BLOCKS, 256, SMEM_GEMM>>>(A, W2 + 2 * DD * DD, b2 + 2 * DD, B);

    // ---- readout ----
    k_final1<<<(NN * 32 + 127) / 128, 128>>>(B, batch, fW, fb, out);
    k_final2<<<(NN + 255) / 256, 256>>>(out, batch);
}